// round 8
// baseline (speedup 1.0000x reference)
#include <cuda_runtime.h>
#include <cstdint>

// Fixed problem geometry (from setup_inputs):
//   fv_label_img : [16, 1, 128, 2048] f32   -> B=16, HW = 262144 = 1<<18
//   fv_pointcloud: [16, 3, 128, 2048] f32
//   bev_h = bev_w = 1024, scale = 1  -> res = 0.1f, half_w = 512
//   out: [16, 1, 1024, 1024] f32
#define HW_SHIFT   18
#define HW         (1 << HW_SHIFT)          // 262144
#define BATCH      16
#define BEV_SHIFT  20
#define BEV_CELLS  (1 << BEV_SHIFT)         // 1024*1024
#define N_POINTS   (BATCH * HW)             // 4,194,304
#define N_OUT      (BATCH * BEV_CELLS)      // 16,777,216
#define EMPTYF     255.0f

// Per-cell winner: max (pixel_index + 1); 0 == untouched.
// INVARIANT: all-zero at every kernel_launch entry.
//   - zero-initialized at module load (.bss)
//   - k_final resets every nonzero uint4 group back to 0 each call
__device__ unsigned int g_prio[N_OUT];

// ---------------------------------------------------------------------------
// Projection. Bit-matches XLA's lowering: x/0.1f -> x * 10.0f (rn reciprocal
// of 0.1f is exactly 10.0f), separate rn-mul / rn-add (no FMA), roundeven.
// ---------------------------------------------------------------------------
__device__ __forceinline__ bool project(float px, float pz, int& cell)
{
    float xf = rintf(__fadd_rn(__fmul_rn(-px, 10.0f), 512.0f));
    float zf = rintf(__fmul_rn(pz, 10.0f));
    if (xf >= 0.0f && xf < 1024.0f && zf >= 0.0f && zf < 1024.0f) {
        cell = (((int)zf) << 10) | (int)xf;
        return true;
    }
    return false;
}

// ---------------------------------------------------------------------------
// Kernel 1: scatter, 8 points/thread. 4 front-batched float4 streaming loads,
// then 8 independent atomicMax ops. Priorities unique within a batch ->
// max == last writer in row-major update order ("last update wins").
// ---------------------------------------------------------------------------
__global__ void k_scatter(const float* __restrict__ pc)
{
    int tid = blockIdx.x * blockDim.x + threadIdx.x;    // 0 .. N_POINTS/8-1
    int g0  = tid << 3;                                  // first point index
    int b   = g0 >> HW_SHIFT;                            // HW % 8 == 0
    int p0  = g0 & (HW - 1);
    const float* base = pc + (size_t)b * (3u << HW_SHIFT);

    float4 px4a = __ldcs((const float4*)(base + p0));
    float4 px4b = __ldcs((const float4*)(base + p0 + 4));
    float4 pz4a = __ldcs((const float4*)(base + (2 << HW_SHIFT) + p0));
    float4 pz4b = __ldcs((const float4*)(base + (2 << HW_SHIFT) + p0 + 4));
    unsigned int* prio_b = g_prio + (b << BEV_SHIFT);

    int cell;
    if (project(px4a.x, pz4a.x, cell)) atomicMax(&prio_b[cell], (unsigned)p0 + 1u);
    if (project(px4a.y, pz4a.y, cell)) atomicMax(&prio_b[cell], (unsigned)p0 + 2u);
    if (project(px4a.z, pz4a.z, cell)) atomicMax(&prio_b[cell], (unsigned)p0 + 3u);
    if (project(px4a.w, pz4a.w, cell)) atomicMax(&prio_b[cell], (unsigned)p0 + 4u);
    if (project(px4b.x, pz4b.x, cell)) atomicMax(&prio_b[cell], (unsigned)p0 + 5u);
    if (project(px4b.y, pz4b.y, cell)) atomicMax(&prio_b[cell], (unsigned)p0 + 6u);
    if (project(px4b.z, pz4b.z, cell)) atomicMax(&prio_b[cell], (unsigned)p0 + 7u);
    if (project(px4b.w, pz4b.w, cell)) atomicMax(&prio_b[cell], (unsigned)p0 + 8u);
}

// ---------------------------------------------------------------------------
// Kernel 2: cell-centric finalize, 8 cells/thread (two independent uint4
// chains for MLP). out[i] = prio[i] ? label[winner] : EMPTY, then restore
// the all-zero invariant with sparse per-uint4 resets (~40% of groups).
// ---------------------------------------------------------------------------
__global__ void k_final(const float* __restrict__ lab, float* __restrict__ out)
{
    int tid = blockIdx.x * blockDim.x + threadIdx.x;    // 0 .. N_OUT/8-1
    int i0  = tid << 3;                                  // first cell index
    int b   = i0 >> BEV_SHIFT;                           // BEV_CELLS % 8 == 0
    const float* lab_b = lab + ((size_t)b << HW_SHIFT);

    uint4 v0 = *(const uint4*)(g_prio + i0);
    uint4 v1 = *(const uint4*)(g_prio + i0 + 4);

    float4 o0, o1;
    o0.x = v0.x ? lab_b[v0.x - 1u] : EMPTYF;
    o0.y = v0.y ? lab_b[v0.y - 1u] : EMPTYF;
    o0.z = v0.z ? lab_b[v0.z - 1u] : EMPTYF;
    o0.w = v0.w ? lab_b[v0.w - 1u] : EMPTYF;
    o1.x = v1.x ? lab_b[v1.x - 1u] : EMPTYF;
    o1.y = v1.y ? lab_b[v1.y - 1u] : EMPTYF;
    o1.z = v1.z ? lab_b[v1.z - 1u] : EMPTYF;
    o1.w = v1.w ? lab_b[v1.w - 1u] : EMPTYF;
    __stcs((float4*)(out + i0), o0);
    __stcs((float4*)(out + i0 + 4), o1);

    if (v0.x | v0.y | v0.z | v0.w)
        *(uint4*)(g_prio + i0) = make_uint4(0u, 0u, 0u, 0u);
    if (v1.x | v1.y | v1.z | v1.w)
        *(uint4*)(g_prio + i0 + 4) = make_uint4(0u, 0u, 0u, 0u);
}

// ---------------------------------------------------------------------------
extern "C" void kernel_launch(void* const* d_in, const int* in_sizes, int n_in,
                              void* d_out, int out_size)
{
    const float* lab = (const float*)d_in[0];
    const float* pc  = (const float*)d_in[1];
    float* out = (float*)d_out;

    k_scatter<<<(N_POINTS / 8) / 256, 256>>>(pc);         // 2048 blocks
    k_final  <<<(N_OUT   / 8) / 256, 256>>>(lab, out);    // 8192 blocks
}

// round 10
// speedup vs baseline: 1.1303x; 1.1303x over previous
#include <cuda_runtime.h>
#include <cstdint>

// Fixed problem geometry (from setup_inputs):
//   fv_label_img : [16, 1, 128, 2048] f32   -> B=16, HW = 262144 = 1<<18
//   fv_pointcloud: [16, 3, 128, 2048] f32
//   bev_h = bev_w = 1024, scale = 1  -> res = 0.1f, half_w = 512
//   out: [16, 1, 1024, 1024] f32
#define HW_SHIFT   18
#define HW         (1 << HW_SHIFT)          // 262144
#define BATCH      16
#define BEV_SHIFT  20
#define BEV_CELLS  (1 << BEV_SHIFT)         // 1024*1024
#define N_POINTS   (BATCH * HW)             // 4,194,304
#define N_OUT      (BATCH * BEV_CELLS)      // 16,777,216
#define EMPTYF     255.0f

// Per-cell winner: max (pixel_index + 1); 0 == untouched.
// INVARIANT: all-zero at every kernel_launch entry.
//   - zero-initialized at module load (.bss)
//   - k_final resets every nonzero uint4 group back to 0 each call
__device__ unsigned int g_prio[N_OUT];

// ---------------------------------------------------------------------------
// Projection. Bit-matches XLA's lowering: x/0.1f -> x * 10.0f (rn reciprocal
// of 0.1f is exactly 10.0f), separate rn-mul / rn-add (no FMA), roundeven.
// ---------------------------------------------------------------------------
__device__ __forceinline__ bool project(float px, float pz, int& cell)
{
    float xf = rintf(__fadd_rn(__fmul_rn(-px, 10.0f), 512.0f));
    float zf = rintf(__fmul_rn(pz, 10.0f));
    if (xf >= 0.0f && xf < 1024.0f && zf >= 0.0f && zf < 1024.0f) {
        cell = (((int)zf) << 10) | (int)xf;
        return true;
    }
    return false;
}

// ---------------------------------------------------------------------------
// Kernel 1: scatter. 4 contiguous points/thread (16B lane stride -> fully
// coalesced float4 loads), two independent planes (x, z) front-batched.
// atomicMax of (pixel_index + 1): priorities unique within a batch, so max
// == last writer in row-major update order ("last update wins").
// ---------------------------------------------------------------------------
__global__ void k_scatter(const float* __restrict__ pc)
{
    int tid = blockIdx.x * blockDim.x + threadIdx.x;    // 0 .. N_POINTS/4-1
    int g0  = tid << 2;                                  // first point index
    int b   = g0 >> HW_SHIFT;                            // HW % 4 == 0
    int p0  = g0 & (HW - 1);
    const float* base = pc + (size_t)b * (3u << HW_SHIFT);

    float4 px4 = __ldcs((const float4*)(base + p0));
    float4 pz4 = __ldcs((const float4*)(base + (2 << HW_SHIFT) + p0));
    unsigned int* prio_b = g_prio + (b << BEV_SHIFT);

    int cell;
    if (project(px4.x, pz4.x, cell)) atomicMax(&prio_b[cell], (unsigned)p0 + 1u);
    if (project(px4.y, pz4.y, cell)) atomicMax(&prio_b[cell], (unsigned)p0 + 2u);
    if (project(px4.z, pz4.z, cell)) atomicMax(&prio_b[cell], (unsigned)p0 + 3u);
    if (project(px4.w, pz4.w, cell)) atomicMax(&prio_b[cell], (unsigned)p0 + 4u);
}

// ---------------------------------------------------------------------------
// Kernel 2: cell-centric finalize. Each thread handles TWO groups of 4
// contiguous cells, the second at a +N_OUT/2 stride: both uint4 loads are
// fully coalesced (16B lane stride) AND independent -> MLP 2 without the
// sector waste that sank the 8-contiguous variant.
//   out[i] = prio[i] ? label[winner] : EMPTY
// then restore the all-zero invariant with sparse per-uint4 resets.
// ---------------------------------------------------------------------------
__global__ void k_final(const float* __restrict__ lab, float* __restrict__ out)
{
    int tid = blockIdx.x * blockDim.x + threadIdx.x;    // 0 .. N_OUT/8-1
    int i0  = tid << 2;                                  // cells [i0, i0+4)
    int i1  = i0 + (N_OUT / 2);                          // cells [i1, i1+4)
    int b0  = i0 >> BEV_SHIFT;
    int b1  = i1 >> BEV_SHIFT;
    const float* lab0 = lab + ((size_t)b0 << HW_SHIFT);
    const float* lab1 = lab + ((size_t)b1 << HW_SHIFT);

    uint4 v0 = *(const uint4*)(g_prio + i0);
    uint4 v1 = *(const uint4*)(g_prio + i1);

    float4 o0, o1;
    o0.x = v0.x ? lab0[v0.x - 1u] : EMPTYF;
    o0.y = v0.y ? lab0[v0.y - 1u] : EMPTYF;
    o0.z = v0.z ? lab0[v0.z - 1u] : EMPTYF;
    o0.w = v0.w ? lab0[v0.w - 1u] : EMPTYF;
    o1.x = v1.x ? lab1[v1.x - 1u] : EMPTYF;
    o1.y = v1.y ? lab1[v1.y - 1u] : EMPTYF;
    o1.z = v1.z ? lab1[v1.z - 1u] : EMPTYF;
    o1.w = v1.w ? lab1[v1.w - 1u] : EMPTYF;
    __stcs((float4*)(out + i0), o0);
    __stcs((float4*)(out + i1), o1);

    if (v0.x | v0.y | v0.z | v0.w)
        *(uint4*)(g_prio + i0) = make_uint4(0u, 0u, 0u, 0u);
    if (v1.x | v1.y | v1.z | v1.w)
        *(uint4*)(g_prio + i1) = make_uint4(0u, 0u, 0u, 0u);
}

// ---------------------------------------------------------------------------
extern "C" void kernel_launch(void* const* d_in, const int* in_sizes, int n_in,
                              void* d_out, int out_size)
{
    const float* lab = (const float*)d_in[0];
    const float* pc  = (const float*)d_in[1];
    float* out = (float*)d_out;

    k_scatter<<<(N_POINTS / 4) / 256, 256>>>(pc);         // 4096 blocks
    k_final  <<<(N_OUT   / 8) / 256, 256>>>(lab, out);    // 8192 blocks
}